// round 8
// baseline (speedup 1.0000x reference)
#include <cuda_runtime.h>
#include <cstdint>

#define Bv 4
#define Sv 4096
#define Hv 32
#define Dv 64
#define NSTEPS 128
#define ROWSTRIDE (Hv * Dv)       // 2048 floats between consecutive s
#define TILE 128                  // rows per tile (4 per warp)
#define CHUNKS 8                  // chunks per (b,h) sequence
#define CHROWS (Sv / CHUNKS)      // 512 rows per chunk
#define NTILES (CHROWS / TILE)    // 4 tiles per chunk
#define TILE_FLOATS (TILE * Dv)   // 8192 floats = 32 KB
#define NBUF 3
#define FULL 0xffffffffu

// cross-CTA chunk aggregates (device globals: no allocation)
__device__ float g_agg[Bv * Hv][CHUNKS][64];
__device__ int   g_flag[Bv * Hv][CHUNKS];

__global__ void reset_flags_kernel() {
    int i = blockIdx.x * blockDim.x + threadIdx.x;
    if (i < Bv * Hv * CHUNKS) ((int*)g_flag)[i] = 0;
}

// sum across the 8 lanes of a row-group (lanes g*8..g*8+7)
__device__ __forceinline__ float grp8_sum(float v) {
    v += __shfl_xor_sync(FULL, v, 4);
    v += __shfl_xor_sync(FULL, v, 2);
    v += __shfl_xor_sync(FULL, v, 1);
    return v;
}
// full 32-lane butterfly sum
__device__ __forceinline__ float warp_sum(float v) {
    v += __shfl_xor_sync(FULL, v, 16);
    v += __shfl_xor_sync(FULL, v, 8);
    v += __shfl_xor_sync(FULL, v, 4);
    v += __shfl_xor_sync(FULL, v, 2);
    v += __shfl_xor_sync(FULL, v, 1);
    return v;
}
// sum across the 4 row-groups (stride-8 lanes), all lanes get result
__device__ __forceinline__ float grpx_sum(float v) {
    v += __shfl_xor_sync(FULL, v, 8);
    v += __shfl_xor_sync(FULL, v, 16);
    return v;
}
// inclusive scan across the 4 row-groups (stride-8 lanes)
__device__ __forceinline__ float scan_grp(float v, int lane) {
    float t = __shfl_up_sync(FULL, v, 8);
    if (lane >= 8) v += t;
    t = __shfl_up_sync(FULL, v, 16);
    if (lane >= 16) v += t;
    return v;
}

__device__ __forceinline__ float4 relu4(float4 a) {
    return make_float4(fmaxf(a.x, 0.f), fmaxf(a.y, 0.f),
                       fmaxf(a.z, 0.f), fmaxf(a.w, 0.f));
}
__device__ __forceinline__ float dot4(float4 a, float4 b) {
    return fmaf(a.x, b.x, fmaf(a.y, b.y, fmaf(a.z, b.z, a.w * b.w)));
}

__device__ __forceinline__ void cp16(float* dst_smem, const float* src) {
    uint32_t d = (uint32_t)__cvta_generic_to_shared(dst_smem);
    asm volatile("cp.async.cg.shared.global [%0], [%1], 16;"
                 :: "r"(d), "l"(src) : "memory");
}

__global__ __launch_bounds__(1024, 1)
void rope_ctx_kernel(const float* __restrict__ q,
                     const float* __restrict__ k,
                     const float* __restrict__ cos_step,
                     const float* __restrict__ sin_step,
                     float* __restrict__ out)
{
    extern __shared__ float smem[];
    float* sk = smem;                         // [NBUF][TILE][64]
    float* sq = smem + NBUF * TILE_FLOATS;    // [NBUF][TILE][64]

    __shared__ float2 s_tab[NSTEPS];
    __shared__ float  s_agg[64][33];
    __shared__ float  s_pref[64][33];

    const int tid  = threadIdx.x;
    const int w    = tid >> 5;
    const int lane = tid & 31;
    const int g    = lane >> 3;               // row group 0..3
    const int j    = lane & 7;                // dim slot within row
    const int bh   = blockIdx.x >> 3;         // CHUNKS = 8
    const int c    = blockIdx.x & 7;
    const int b    = bh >> 5;                 // H = 32
    const int h    = bh & 31;

    if (tid < NSTEPS) {
        s_tab[tid] = make_float2(cos_step[tid * Dv], sin_step[tid * Dv]);
    }

    const size_t base = (size_t)b * Sv * ROWSTRIDE + (size_t)h * Dv
                      + (size_t)c * CHROWS * ROWSTRIDE;   // chunk base
    const float* qg = q + base;
    const float* kg = k + base;
    float* og = out + base;
    const size_t KOUT = (size_t)Bv * Sv * ROWSTRIDE;

    const int dx = 4 * j;              // x dims: dx..dx+3 ; y dims: 32+dx..
    const int dy = 32 + 4 * j;
    const int r  = (w << 2) + g;       // this thread's row within a tile
    const int sodx = (r << 6) + dx;
    const int sody = (r << 6) + dy;

    // per-thread-exact staging: a thread copies ONLY the words it will read
    auto issue = [&](int t) {
        if (t < NTILES) {
            const int p = t % NBUF;
            float* skb = sk + p * TILE_FLOATS;
            float* sqb = sq + p * TILE_FLOATS;
            const size_t go = (size_t)(t * TILE + r) * ROWSTRIDE;
            cp16(skb + sodx, kg + go + dx);
            cp16(skb + sody, kg + go + dy);
            cp16(sqb + sodx, qg + go + dx);
            cp16(sqb + sody, qg + go + dy);
        }
        asm volatile("cp.async.commit_group;" ::: "memory");
    };

    // kick off pass-2 prefetch before the aggregate pass (overlaps it)
    issue(0);
    issue(1);

    // ================= pass 1: this chunk's kn aggregate =====================
    float4 sxa = make_float4(0.f, 0.f, 0.f, 0.f);
    float4 sya = make_float4(0.f, 0.f, 0.f, 0.f);
    #pragma unroll
    for (int tt = 0; tt < NTILES; ++tt) {
        const float* kp = kg + (size_t)(tt * TILE + r) * ROWSTRIDE;
        float4 kx = __ldg((const float4*)(kp + dx));
        float4 ky = __ldg((const float4*)(kp + dy));
        float4 knx = relu4(kx), kny = relu4(ky);
        float ss = grp8_sum(dot4(knx, knx) + dot4(kny, kny));
        float kinv = __fdividef(1.f, sqrtf(ss) + 1e-6f);
        sxa.x = fmaf(knx.x, kinv, sxa.x); sxa.y = fmaf(knx.y, kinv, sxa.y);
        sxa.z = fmaf(knx.z, kinv, sxa.z); sxa.w = fmaf(knx.w, kinv, sxa.w);
        sya.x = fmaf(kny.x, kinv, sya.x); sya.y = fmaf(kny.y, kinv, sya.y);
        sya.z = fmaf(kny.z, kinv, sya.z); sya.w = fmaf(kny.w, kinv, sya.w);
    }
    // fold the 4 row-groups together (each lane then has its dims' warp sum)
    sxa.x = grpx_sum(sxa.x); sxa.y = grpx_sum(sxa.y);
    sxa.z = grpx_sum(sxa.z); sxa.w = grpx_sum(sxa.w);
    sya.x = grpx_sum(sya.x); sya.y = grpx_sum(sya.y);
    sya.z = grpx_sum(sya.z); sya.w = grpx_sum(sya.w);
    if (g == 0) {
        s_agg[dx    ][w] = sxa.x; s_agg[dx + 1][w] = sxa.y;
        s_agg[dx + 2][w] = sxa.z; s_agg[dx + 3][w] = sxa.w;
        s_agg[dy    ][w] = sya.x; s_agg[dy + 1][w] = sya.y;
        s_agg[dy + 2][w] = sya.z; s_agg[dy + 3][w] = sya.w;
    }
    __syncthreads();
    {   // warp w totals dims 2w, 2w+1 across the 32 warps; publish to global
        float v0 = warp_sum(s_agg[2 * w    ][lane]);
        float v1 = warp_sum(s_agg[2 * w + 1][lane]);
        if (lane == 0) {
            g_agg[bh][c][2 * w    ] = v0;
            g_agg[bh][c][2 * w + 1] = v1;
        }
    }
    __threadfence();
    __syncthreads();
    if (tid == 0) atomicExch(&g_flag[bh][c], 1);

    // ================= lookback: sum predecessor chunk aggregates ===========
    if (tid < c) {
        volatile int* f = &g_flag[bh][tid];
        while (*f == 0) { __nanosleep(64); }
    }
    __threadfence();
    __syncthreads();

    float4 basex = make_float4(0.f, 0.f, 0.f, 0.f);
    float4 basey = make_float4(0.f, 0.f, 0.f, 0.f);
    for (int cc = 0; cc < c; ++cc) {
        float4 ax = *(const float4*)&g_agg[bh][cc][dx];
        float4 ay = *(const float4*)&g_agg[bh][cc][dy];
        basex.x += ax.x; basex.y += ax.y; basex.z += ax.z; basex.w += ax.w;
        basey.x += ay.x; basey.y += ay.y; basey.z += ay.z; basey.w += ay.w;
    }
    __syncthreads();   // s_agg reuse below needs everyone past the reduce

    // ================= pass 2: R5 tile loop over this chunk ==================
    for (int t = 0; t < NTILES; ++t) {
        const int p = t % NBUF;
        asm volatile("cp.async.wait_group 1;" ::: "memory");
        issue(t + 2);

        const float* skb = sk + p * TILE_FLOATS;
        const float* sqb = sq + p * TILE_FLOATS;
        float4 kx = *(const float4*)(skb + sodx);
        float4 ky = *(const float4*)(skb + sody);
        float4 qx = *(const float4*)(sqb + sodx);
        float4 qy = *(const float4*)(sqb + sody);

        float4 knx = relu4(kx), kny = relu4(ky);
        float ss = grp8_sum(dot4(knx, knx) + dot4(kny, kny));
        float kinv = __fdividef(1.f, sqrtf(ss) + 1e-6f);
        knx.x *= kinv; knx.y *= kinv; knx.z *= kinv; knx.w *= kinv;
        kny.x *= kinv; kny.y *= kinv; kny.z *= kinv; kny.w *= kinv;

        float4 ix, iy;
        ix.x = scan_grp(knx.x, lane); ix.y = scan_grp(knx.y, lane);
        ix.z = scan_grp(knx.z, lane); ix.w = scan_grp(knx.w, lane);
        iy.x = scan_grp(kny.x, lane); iy.y = scan_grp(kny.y, lane);
        iy.z = scan_grp(kny.z, lane); iy.w = scan_grp(kny.w, lane);

        if (g == 3) {
            s_agg[dx    ][w] = ix.x; s_agg[dx + 1][w] = ix.y;
            s_agg[dx + 2][w] = ix.z; s_agg[dx + 3][w] = ix.w;
            s_agg[dy    ][w] = iy.x; s_agg[dy + 1][w] = iy.y;
            s_agg[dy + 2][w] = iy.z; s_agg[dy + 3][w] = iy.w;
        }

        float4 qrx = relu4(qx), qry = relu4(qy);
        float qs = grp8_sum(dot4(qrx, qrx) + dot4(qry, qry));
        float qinv = __fdividef(1.f, sqrtf(qs) + 1e-6f);

        __syncthreads();                   // B1: s_agg ready

        #pragma unroll
        for (int dd = 0; dd < 2; ++dd) {
            const int d = 2 * w + dd;
            float v = s_agg[d][lane];
            float u;
            u = __shfl_up_sync(FULL, v, 1);  if (lane >= 1)  v += u;
            u = __shfl_up_sync(FULL, v, 2);  if (lane >= 2)  v += u;
            u = __shfl_up_sync(FULL, v, 4);  if (lane >= 4)  v += u;
            u = __shfl_up_sync(FULL, v, 8);  if (lane >= 8)  v += u;
            u = __shfl_up_sync(FULL, v, 16); if (lane >= 16) v += u;
            s_pref[d][lane + 1] = v;        // exclusive at [w], total at [32]
            if (lane == 0) s_pref[d][0] = 0.f;
        }
        __syncthreads();                   // B2: s_pref ready

        float4 cx, cy;
        cx.x = basex.x + s_pref[dx    ][w] + ix.x;
        cx.y = basex.y + s_pref[dx + 1][w] + ix.y;
        cx.z = basex.z + s_pref[dx + 2][w] + ix.z;
        cx.w = basex.w + s_pref[dx + 3][w] + ix.w;
        cy.x = basey.x + s_pref[dy    ][w] + iy.x;
        cy.y = basey.y + s_pref[dy + 1][w] + iy.y;
        cy.z = basey.z + s_pref[dy + 2][w] + iy.z;
        cy.w = basey.w + s_pref[dy + 3][w] + iy.w;

        basex.x += s_pref[dx    ][32]; basex.y += s_pref[dx + 1][32];
        basex.z += s_pref[dx + 2][32]; basex.w += s_pref[dx + 3][32];
        basey.x += s_pref[dy    ][32]; basey.y += s_pref[dy + 1][32];
        basey.z += s_pref[dy + 2][32]; basey.w += s_pref[dy + 3][32];

        float dot = grp8_sum(dot4(qrx, cx) + dot4(qry, cy)) * qinv;

        float pp = fminf(fmaxf(dot * (1.f / 32.f), 0.f), 127.f);
        float pf = floorf(pp);
        int   fi = (int)pf;
        int   ci = (int)ceilf(pp);
        float fr = pp - pf;
        float2 t0 = s_tab[fi], t1 = s_tab[ci];
        float cn = fmaf(fr, t1.x - t0.x, t0.x);
        float sn = fmaf(fr, t1.y - t0.y, t0.y);

        float4 oqx, oqy, okx, oky;
        oqx.x = fmaf(qx.x, cn, -qy.x * sn);  oqy.x = fmaf(qy.x, cn, qx.x * sn);
        oqx.y = fmaf(qx.y, cn, -qy.y * sn);  oqy.y = fmaf(qy.y, cn, qx.y * sn);
        oqx.z = fmaf(qx.z, cn, -qy.z * sn);  oqy.z = fmaf(qy.z, cn, qx.z * sn);
        oqx.w = fmaf(qx.w, cn, -qy.w * sn);  oqy.w = fmaf(qy.w, cn, qx.w * sn);
        okx.x = fmaf(kx.x, cn, -ky.x * sn);  oky.x = fmaf(ky.x, cn, kx.x * sn);
        okx.y = fmaf(kx.y, cn, -ky.y * sn);  oky.y = fmaf(ky.y, cn, kx.y * sn);
        okx.z = fmaf(kx.z, cn, -ky.z * sn);  oky.z = fmaf(ky.z, cn, kx.z * sn);
        okx.w = fmaf(kx.w, cn, -ky.w * sn);  oky.w = fmaf(ky.w, cn, kx.w * sn);

        const size_t ro = (size_t)(t * TILE + r) * ROWSTRIDE + dx;
        *(float4*)(og + ro)             = oqx;
        *(float4*)(og + ro + 32)        = oqy;
        *(float4*)(og + KOUT + ro)      = okx;
        *(float4*)(og + KOUT + ro + 32) = oky;
    }
}

extern "C" void kernel_launch(void* const* d_in, const int* in_sizes, int n_in,
                              void* d_out, int out_size)
{
    const float* q        = (const float*)d_in[0];
    const float* k        = (const float*)d_in[1];
    // d_in[2] = v (unused by the reference math)
    const float* cos_step = (const float*)d_in[3];
    const float* sin_step = (const float*)d_in[4];
    // d_in[5] = offset (unused by the reference math)

    reset_flags_kernel<<<1, 1024>>>();

    const size_t dyn = (size_t)2 * NBUF * TILE_FLOATS * sizeof(float); // 192 KB
    cudaFuncSetAttribute(rope_ctx_kernel,
                         cudaFuncAttributeMaxDynamicSharedMemorySize, (int)dyn);
    rope_ctx_kernel<<<Bv * Hv * CHUNKS, 1024, dyn>>>(q, k, cos_step, sin_step,
                                                     (float*)d_out);
}

// round 9
// speedup vs baseline: 1.0130x; 1.0130x over previous
#include <cuda_runtime.h>
#include <cstdint>

#define Bv 4
#define Sv 4096
#define Hv 32
#define Dv 64
#define NSTEPS 128
#define ROWSTRIDE (Hv * Dv)       // 2048 floats between consecutive s
#define THREADS 512
#define WARPS 16
#define TILE 64                   // rows per tile (4 per warp, 16 warps)
#define CHUNKS 16                 // chunks per (b,h) sequence
#define CHROWS (Sv / CHUNKS)      // 256 rows per chunk
#define NTILES (CHROWS / TILE)    // 4 tiles per chunk
#define TILE_FLOATS (TILE * Dv)   // 4096 floats = 16 KB
#define NBUF 3
#define FULL 0xffffffffu

// cross-CTA chunk aggregates (device globals: no allocation)
__device__ __align__(256) float g_agg[Bv * Hv][CHUNKS][64];
__device__ int   g_flag[Bv * Hv][CHUNKS];

__global__ void reset_flags_kernel() {
    int i = blockIdx.x * blockDim.x + threadIdx.x;
    if (i < Bv * Hv * CHUNKS) ((int*)g_flag)[i] = 0;
}

// sum across the 8 lanes of a row-group (lanes g*8..g*8+7)
__device__ __forceinline__ float grp8_sum(float v) {
    v += __shfl_xor_sync(FULL, v, 4);
    v += __shfl_xor_sync(FULL, v, 2);
    v += __shfl_xor_sync(FULL, v, 1);
    return v;
}
// sum across the 4 row-groups (stride-8 lanes), all lanes get result
__device__ __forceinline__ float grpx_sum(float v) {
    v += __shfl_xor_sync(FULL, v, 8);
    v += __shfl_xor_sync(FULL, v, 16);
    return v;
}
// inclusive scan across the 4 row-groups (stride-8 lanes)
__device__ __forceinline__ float scan_grp(float v, int lane) {
    float t = __shfl_up_sync(FULL, v, 8);
    if (lane >= 8) v += t;
    t = __shfl_up_sync(FULL, v, 16);
    if (lane >= 16) v += t;
    return v;
}

__device__ __forceinline__ float4 relu4(float4 a) {
    return make_float4(fmaxf(a.x, 0.f), fmaxf(a.y, 0.f),
                       fmaxf(a.z, 0.f), fmaxf(a.w, 0.f));
}
__device__ __forceinline__ float dot4(float4 a, float4 b) {
    return fmaf(a.x, b.x, fmaf(a.y, b.y, fmaf(a.z, b.z, a.w * b.w)));
}

__device__ __forceinline__ void cp16(float* dst_smem, const float* src) {
    uint32_t d = (uint32_t)__cvta_generic_to_shared(dst_smem);
    asm volatile("cp.async.cg.shared.global [%0], [%1], 16;"
                 :: "r"(d), "l"(src) : "memory");
}

__global__ __launch_bounds__(THREADS, 2)
void rope_ctx_kernel(const float* __restrict__ q,
                     const float* __restrict__ k,
                     const float* __restrict__ cos_step,
                     const float* __restrict__ sin_step,
                     float* __restrict__ out)
{
    extern __shared__ float smem[];
    float* sk = smem;                         // [NBUF][TILE][64]
    float* sq = smem + NBUF * TILE_FLOATS;    // [NBUF][TILE][64]

    __shared__ float2 s_tab[NSTEPS];
    __shared__ float  s_agg[64][18];          // per-dim per-warp aggregates
    __shared__ float  s_pref[64][18];         // [d][w+1] inclusive; [d][0]=0

    const int tid  = threadIdx.x;
    const int w    = tid >> 5;                // 0..15
    const int lane = tid & 31;
    const int g    = lane >> 3;               // row group 0..3
    const int j    = lane & 7;                // dim slot within row
    const int bh   = blockIdx.x >> 4;         // CHUNKS = 16
    const int c    = blockIdx.x & 15;
    const int b    = bh >> 5;                 // H = 32
    const int h    = bh & 31;

    if (tid < NSTEPS) {
        s_tab[tid] = make_float2(cos_step[tid * Dv], sin_step[tid * Dv]);
    }

    const size_t base = (size_t)b * Sv * ROWSTRIDE + (size_t)h * Dv
                      + (size_t)c * CHROWS * ROWSTRIDE;   // chunk base
    const float* qg = q + base;
    const float* kg = k + base;
    float* og = out + base;
    const size_t KOUT = (size_t)Bv * Sv * ROWSTRIDE;

    const int dx = 4 * j;              // x dims: dx..dx+3 ; y dims: 32+dx..
    const int dy = 32 + 4 * j;
    const int r  = (w << 2) + g;       // this thread's row within a tile 0..63
    const int sodx = (r << 6) + dx;
    const int sody = (r << 6) + dy;

    // per-thread-exact staging: a thread copies ONLY the words it will read
    auto issue = [&](int t) {
        if (t < NTILES) {
            const int p = t % NBUF;
            float* skb = sk + p * TILE_FLOATS;
            float* sqb = sq + p * TILE_FLOATS;
            const size_t go = (size_t)(t * TILE + r) * ROWSTRIDE;
            cp16(skb + sodx, kg + go + dx);
            cp16(skb + sody, kg + go + dy);
            cp16(sqb + sodx, qg + go + dx);
            cp16(sqb + sody, qg + go + dy);
        }
        asm volatile("cp.async.commit_group;" ::: "memory");
    };

    // kick off pass-2 prefetch before the aggregate pass (overlaps it)
    issue(0);
    issue(1);

    // ================= pass 1: this chunk's kn aggregate =====================
    float4 sxa = make_float4(0.f, 0.f, 0.f, 0.f);
    float4 sya = make_float4(0.f, 0.f, 0.f, 0.f);
    #pragma unroll
    for (int tt = 0; tt < NTILES; ++tt) {
        const float* kp = kg + (size_t)(tt * TILE + r) * ROWSTRIDE;
        float4 kx = __ldg((const float4*)(kp + dx));
        float4 ky = __ldg((const float4*)(kp + dy));
        float4 knx = relu4(kx), kny = relu4(ky);
        float ss = grp8_sum(dot4(knx, knx) + dot4(kny, kny));
        float kinv = __fdividef(1.f, sqrtf(ss) + 1e-6f);
        sxa.x = fmaf(knx.x, kinv, sxa.x); sxa.y = fmaf(knx.y, kinv, sxa.y);
        sxa.z = fmaf(knx.z, kinv, sxa.z); sxa.w = fmaf(knx.w, kinv, sxa.w);
        sya.x = fmaf(kny.x, kinv, sya.x); sya.y = fmaf(kny.y, kinv, sya.y);
        sya.z = fmaf(kny.z, kinv, sya.z); sya.w = fmaf(kny.w, kinv, sya.w);
    }
    // fold the 4 row-groups (each lane then has its dims' warp sum)
    sxa.x = grpx_sum(sxa.x); sxa.y = grpx_sum(sxa.y);
    sxa.z = grpx_sum(sxa.z); sxa.w = grpx_sum(sxa.w);
    sya.x = grpx_sum(sya.x); sya.y = grpx_sum(sya.y);
    sya.z = grpx_sum(sya.z); sya.w = grpx_sum(sya.w);
    if (g == 0) {
        s_agg[dx    ][w] = sxa.x; s_agg[dx + 1][w] = sxa.y;
        s_agg[dx + 2][w] = sxa.z; s_agg[dx + 3][w] = sxa.w;
        s_agg[dy    ][w] = sya.x; s_agg[dy + 1][w] = sya.y;
        s_agg[dy + 2][w] = sya.z; s_agg[dy + 3][w] = sya.w;
    }
    __syncthreads();
    {   // warp w totals dims 4w..4w+3 across the 16 warps; publish to global
        #pragma unroll
        for (int dd = 0; dd < 4; ++dd) {
            const int d = 4 * w + dd;
            float v = (lane < WARPS) ? s_agg[d][lane] : 0.f;
            v += __shfl_xor_sync(FULL, v, 8);
            v += __shfl_xor_sync(FULL, v, 4);
            v += __shfl_xor_sync(FULL, v, 2);
            v += __shfl_xor_sync(FULL, v, 1);
            if (lane == 0) g_agg[bh][c][d] = v;
        }
    }
    __threadfence();
    __syncthreads();
    if (tid == 0) atomicExch(&g_flag[bh][c], 1);

    // ================= lookback: sum predecessor chunk aggregates ===========
    if (tid < c) {
        volatile int* f = &g_flag[bh][tid];
        while (*f == 0) { __nanosleep(64); }
    }
    __threadfence();
    __syncthreads();

    float4 basex = make_float4(0.f, 0.f, 0.f, 0.f);
    float4 basey = make_float4(0.f, 0.f, 0.f, 0.f);
    for (int cc = 0; cc < c; ++cc) {
        float4 ax = *(const float4*)&g_agg[bh][cc][dx];
        float4 ay = *(const float4*)&g_agg[bh][cc][dy];
        basex.x += ax.x; basex.y += ax.y; basex.z += ax.z; basex.w += ax.w;
        basey.x += ay.x; basey.y += ay.y; basey.z += ay.z; basey.w += ay.w;
    }
    __syncthreads();   // everyone done reading s_agg before pass 2 rewrites it

    // ================= pass 2: R5 tile loop over this chunk ==================
    for (int t = 0; t < NTILES; ++t) {
        const int p = t % NBUF;
        asm volatile("cp.async.wait_group 1;" ::: "memory");
        issue(t + 2);

        const float* skb = sk + p * TILE_FLOATS;
        const float* sqb = sq + p * TILE_FLOATS;
        float4 kx = *(const float4*)(skb + sodx);
        float4 ky = *(const float4*)(skb + sody);
        float4 qx = *(const float4*)(sqb + sodx);
        float4 qy = *(const float4*)(sqb + sody);

        float4 knx = relu4(kx), kny = relu4(ky);
        float ss = grp8_sum(dot4(knx, knx) + dot4(kny, kny));
        float kinv = __fdividef(1.f, sqrtf(ss) + 1e-6f);
        knx.x *= kinv; knx.y *= kinv; knx.z *= kinv; knx.w *= kinv;
        kny.x *= kinv; kny.y *= kinv; kny.z *= kinv; kny.w *= kinv;

        float4 ix, iy;
        ix.x = scan_grp(knx.x, lane); ix.y = scan_grp(knx.y, lane);
        ix.z = scan_grp(knx.z, lane); ix.w = scan_grp(knx.w, lane);
        iy.x = scan_grp(kny.x, lane); iy.y = scan_grp(kny.y, lane);
        iy.z = scan_grp(kny.z, lane); iy.w = scan_grp(kny.w, lane);

        if (g == 3) {                  // group 3 holds the warp's 4-row totals
            s_agg[dx    ][w] = ix.x; s_agg[dx + 1][w] = ix.y;
            s_agg[dx + 2][w] = ix.z; s_agg[dx + 3][w] = ix.w;
            s_agg[dy    ][w] = iy.x; s_agg[dy + 1][w] = iy.y;
            s_agg[dy + 2][w] = iy.z; s_agg[dy + 3][w] = iy.w;
        }

        float4 qrx = relu4(qx), qry = relu4(qy);
        float qs = grp8_sum(dot4(qrx, qrx) + dot4(qry, qry));
        float qinv = __fdividef(1.f, sqrtf(qs) + 1e-6f);

        __syncthreads();                   // B1: s_agg ready

        // cross-warp scan: warp w scans dims 4w..4w+3 over 16 warp entries
        #pragma unroll
        for (int dd = 0; dd < 4; ++dd) {
            const int d = 4 * w + dd;
            float v = (lane < WARPS) ? s_agg[d][lane] : 0.f;
            float u;
            u = __shfl_up_sync(FULL, v, 1);  if (lane >= 1) v += u;
            u = __shfl_up_sync(FULL, v, 2);  if (lane >= 2) v += u;
            u = __shfl_up_sync(FULL, v, 4);  if (lane >= 4) v += u;
            u = __shfl_up_sync(FULL, v, 8);  if (lane >= 8) v += u;
            if (lane < WARPS) s_pref[d][lane + 1] = v;  // excl at [w], tot [16]
            if (lane == 0) s_pref[d][0] = 0.f;
        }
        __syncthreads();                   // B2: s_pref ready

        float4 cx, cy;
        cx.x = basex.x + s_pref[dx    ][w] + ix.x;
        cx.y = basex.y + s_pref[dx + 1][w] + ix.y;
        cx.z = basex.z + s_pref[dx + 2][w] + ix.z;
        cx.w = basex.w + s_pref[dx + 3][w] + ix.w;
        cy.x = basey.x + s_pref[dy    ][w] + iy.x;
        cy.y = basey.y + s_pref[dy + 1][w] + iy.y;
        cy.z = basey.z + s_pref[dy + 2][w] + iy.z;
        cy.w = basey.w + s_pref[dy + 3][w] + iy.w;

        basex.x += s_pref[dx    ][WARPS]; basex.y += s_pref[dx + 1][WARPS];
        basex.z += s_pref[dx + 2][WARPS]; basex.w += s_pref[dx + 3][WARPS];
        basey.x += s_pref[dy    ][WARPS]; basey.y += s_pref[dy + 1][WARPS];
        basey.z += s_pref[dy + 2][WARPS]; basey.w += s_pref[dy + 3][WARPS];

        float dot = grp8_sum(dot4(qrx, cx) + dot4(qry, cy)) * qinv;

        float pp = fminf(fmaxf(dot * (1.f / 32.f), 0.f), 127.f);
        float pf = floorf(pp);
        int   fi = (int)pf;
        int   ci = (int)ceilf(pp);
        float fr = pp - pf;
        float2 t0 = s_tab[fi], t1 = s_tab[ci];
        float cn = fmaf(fr, t1.x - t0.x, t0.x);
        float sn = fmaf(fr, t1.y - t0.y, t0.y);

        float4 oqx, oqy, okx, oky;
        oqx.x = fmaf(qx.x, cn, -qy.x * sn);  oqy.x = fmaf(qy.x, cn, qx.x * sn);
        oqx.y = fmaf(qx.y, cn, -qy.y * sn);  oqy.y = fmaf(qy.y, cn, qx.y * sn);
        oqx.z = fmaf(qx.z, cn, -qy.z * sn);  oqy.z = fmaf(qy.z, cn, qx.z * sn);
        oqx.w = fmaf(qx.w, cn, -qy.w * sn);  oqy.w = fmaf(qy.w, cn, qx.w * sn);
        okx.x = fmaf(kx.x, cn, -ky.x * sn);  oky.x = fmaf(ky.x, cn, kx.x * sn);
        okx.y = fmaf(kx.y, cn, -ky.y * sn);  oky.y = fmaf(ky.y, cn, kx.y * sn);
        okx.z = fmaf(kx.z, cn, -ky.z * sn);  oky.z = fmaf(ky.z, cn, kx.z * sn);
        okx.w = fmaf(kx.w, cn, -ky.w * sn);  oky.w = fmaf(ky.w, cn, kx.w * sn);

        const size_t ro = (size_t)(t * TILE + r) * ROWSTRIDE + dx;
        *(float4*)(og + ro)             = oqx;
        *(float4*)(og + ro + 32)        = oqy;
        *(float4*)(og + KOUT + ro)      = okx;
        *(float4*)(og + KOUT + ro + 32) = oky;
    }
}

extern "C" void kernel_launch(void* const* d_in, const int* in_sizes, int n_in,
                              void* d_out, int out_size)
{
    const float* q        = (const float*)d_in[0];
    const float* k        = (const float*)d_in[1];
    // d_in[2] = v (unused by the reference math)
    const float* cos_step = (const float*)d_in[3];
    const float* sin_step = (const float*)d_in[4];
    // d_in[5] = offset (unused by the reference math)

    reset_flags_kernel<<<2, 1024>>>();

    const size_t dyn = (size_t)2 * NBUF * TILE_FLOATS * sizeof(float); // 96 KB
    cudaFuncSetAttribute(rope_ctx_kernel,
                         cudaFuncAttributeMaxDynamicSharedMemorySize, (int)dyn);
    rope_ctx_kernel<<<Bv * Hv * CHUNKS, THREADS, dyn>>>(q, k, cos_step,
                                                        sin_step,
                                                        (float*)d_out);
}